// round 14
// baseline (speedup 1.0000x reference)
#include <cuda_runtime.h>
#include <cuda_fp16.h>
#include <cstdint>

typedef __half fp16;

#define NROIS 1000
#define DFEAT 12544
#define MPAD  1024

// ---------------- persistent scratch (zero-init) -------------------------------
__device__ fp16 g_xh [MPAD * DFEAT];
__device__ fp16 g_w1h[DFEAT * 1024];   // [K][N], single fp16
__device__ fp16 g_w2h[1024 * 1024];
__device__ fp16 g_whh[1024 * 512];     // combined heads [K=1024][N=512 padded]
__device__ fp16 g_f1h[MPAD * 1024];
__device__ fp16 g_f2h[MPAD * 1024];
__device__ float g_bcomb[512];
// transposed feature maps [H][W][C] fp16
__device__ fp16 g_ft2[256 * 256 * 256];
__device__ fp16 g_ft3[128 * 128 * 256];
__device__ fp16 g_ft4[64 * 64 * 256];
__device__ fp16 g_ft5[32 * 32 * 256];

// ---------------- helpers ------------------------------------------------------
__device__ __forceinline__ uint32_t s2u(const void* p) {
    uint32_t a;
    asm("{ .reg .u64 t; cvta.to.shared.u64 t, %1; cvt.u32.u64 %0, t; }" : "=r"(a) : "l"(p));
    return a;
}
__device__ __forceinline__ void cp16(uint32_t s, const void* g) {
    asm volatile("cp.async.cg.shared.global [%0], [%1], 16;" :: "r"(s), "l"(g) : "memory");
}
__device__ __forceinline__ void cp_commit() {
    asm volatile("cp.async.commit_group;" ::: "memory");
}
__device__ __forceinline__ void cp_wait2() {
    asm volatile("cp.async.wait_group 2;" ::: "memory");
}
__device__ __forceinline__ void ldsm4(uint32_t* r, uint32_t a) {
    asm volatile("ldmatrix.sync.aligned.m8n8.x4.shared.b16 {%0,%1,%2,%3}, [%4];"
                 : "=r"(r[0]), "=r"(r[1]), "=r"(r[2]), "=r"(r[3]) : "r"(a));
}
__device__ __forceinline__ void ldsm4t(uint32_t* r, uint32_t a) {
    asm volatile("ldmatrix.sync.aligned.m8n8.x4.trans.shared.b16 {%0,%1,%2,%3}, [%4];"
                 : "=r"(r[0]), "=r"(r[1]), "=r"(r[2]), "=r"(r[3]) : "r"(a));
}
__device__ __forceinline__ void mma16816(float* c, const uint32_t* a, const uint32_t* b) {
    asm volatile(
        "mma.sync.aligned.m16n8k16.row.col.f32.f16.f16.f32 "
        "{%0,%1,%2,%3}, {%4,%5,%6,%7}, {%8,%9}, {%0,%1,%2,%3};"
        : "+f"(c[0]), "+f"(c[1]), "+f"(c[2]), "+f"(c[3])
        : "r"(a[0]), "r"(a[1]), "r"(a[2]), "r"(a[3]), "r"(b[0]), "r"(b[1]));
}

// ---------------- stage1: ftrans + weight prep, one launch ---------------------
#define FT_NB2 16384
#define FT_NB3 4096
#define FT_NB4 1024
#define FT_NB5 256
#define FT_TOT (FT_NB2 + FT_NB3 + FT_NB4 + FT_NB5)   // 21760
#define NB_W1 12544
#define NB_W2 1024
#define NB_HD 2048
#define ST1_TOT (FT_TOT + NB_W1 + NB_W2 + NB_HD + 1)

__global__ void stage1_all(const float* __restrict__ f2, const float* __restrict__ f3,
                           const float* __restrict__ f4, const float* __restrict__ f5,
                           fp16* __restrict__ t2o, fp16* __restrict__ t3o,
                           fp16* __restrict__ t4o, fp16* __restrict__ t5o,
                           const float4* __restrict__ W1, const float4* __restrict__ W2,
                           const float* __restrict__ Wloc, const float* __restrict__ Wsc,
                           const float* __restrict__ bloc, const float* __restrict__ bsc,
                           fp16* __restrict__ w1h, fp16* __restrict__ w2h,
                           fp16* __restrict__ whh, float* __restrict__ bcomb)
{
    const int tid = threadIdx.x;
    int b = blockIdx.x;
    if (b < FT_TOT) {
        // feature transpose [C][H][W] fp32 -> [H][W][C] fp16
        __shared__ float t[32][33];
        const float* f; fp16* ft; int H;
        if (b < FT_NB2)                         { f = f2; ft = t2o; H = 256; }
        else if (b < FT_NB2 + FT_NB3)           { b -= FT_NB2; f = f3; ft = t3o; H = 128; }
        else if (b < FT_NB2 + FT_NB3 + FT_NB4)  { b -= FT_NB2 + FT_NB3; f = f4; ft = t4o; H = 64; }
        else                                    { b -= FT_NB2 + FT_NB3 + FT_NB4; f = f5; ft = t5o; H = 32; }
        const int W = H;
        const int wT = H >> 5;
        const int w0 = (b % wT) * 32;
        const int h  = (b / wT) % H;
        const int c0 = (b / (wT * H)) * 32;
        const int tx = tid & 31, ty = tid >> 5;
        #pragma unroll
        for (int r = 0; r < 4; ++r) {
            const int c = c0 + ty + r * 8;
            t[ty + r * 8][tx] = f[((size_t)c * H + h) * W + w0 + tx];
        }
        __syncthreads();
        #pragma unroll
        for (int r = 0; r < 4; ++r) {
            const int w = w0 + ty + r * 8;
            ft[((size_t)h * W + w) * 256 + c0 + tx] = __float2half_rn(t[tx][ty + r * 8]);
        }
        return;
    }
    b -= FT_TOT;
    if (b < NB_W1 + NB_W2) {
        const bool isW1 = (b < NB_W1);
        const int i = (isW1 ? b : b - NB_W1) * 256 + tid;
        const float4 v = isW1 ? W1[i] : W2[i];
        __half2* H2 = (__half2*)(isW1 ? w1h : w2h);
        H2[2 * i]     = __halves2half2(__float2half_rn(v.x), __float2half_rn(v.y));
        H2[2 * i + 1] = __halves2half2(__float2half_rn(v.z), __float2half_rn(v.w));
    } else if (b < NB_W1 + NB_W2 + NB_HD) {
        const int idx = (b - NB_W1 - NB_W2) * 256 + tid;
        const int k = idx >> 9, n = idx & 511;
        float v = 0.0f;
        if (n < 324)      v = Wloc[k * 324 + n];
        else if (n < 405) v = Wsc[k * 81 + (n - 324)];
        whh[idx] = __float2half_rn(v);
    } else {
        for (int i = tid; i < 512; i += 256)
            bcomb[i] = (i < 324) ? bloc[i] : ((i < 405) ? bsc[i - 324] : 0.0f);
    }
}

// ---------------- ROI align, fp16 uint2 gather (4 channels/thread) -------------
__global__ void roi_align3(const fp16* __restrict__ ft2, const fp16* __restrict__ ft3,
                           const fp16* __restrict__ ft4, const fp16* __restrict__ ft5,
                           const float* __restrict__ rois,
                           fp16* __restrict__ xh)
{
    extern __shared__ float s[];   // 12544 floats
    const int r = blockIdx.x;
    const int tid = threadIdx.x;
    const int cg = tid & 63;
    const int half = tid >> 6;

    __shared__ int   s_y0[14], s_y1[14], s_x0[14], s_x1[14];
    __shared__ float s_ly[14], s_lx[14];

    const float ry1 = rois[r * 4 + 0];
    const float rx1 = rois[r * 4 + 1];
    const float ry2 = rois[r * 4 + 2];
    const float rx2 = rois[r * 4 + 3];

    const float hh = ry2 - ry1 + 1.0f;
    const float ww = rx2 - rx1 + 1.0f;
    float lv = floorf(logf(sqrtf(hh * ww) / 224.0f) / 0.693147f + 4.0f);
    lv = fminf(fmaxf(lv, 2.0f), 5.0f);
    const int lvl = (int)lv;

    int H; const fp16* ft;
    if (lvl == 2)      { H = 256; ft = ft2; }
    else if (lvl == 3) { H = 128; ft = ft3; }
    else if (lvl == 4) { H = 64;  ft = ft4; }
    else               { H = 32;  ft = ft5; }
    const int W = H;

    const float fm = (float)(H - 1);
    const float gy1 = ry1 * fm / 1023.0f;
    const float gx1 = rx1 * fm / 1023.0f;
    const float gy2 = ry2 * fm / 1023.0f;
    const float gx2 = rx2 * fm / 1023.0f;
    const float hs = (gy2 - gy1) / 14.0f;
    const float ws = (gx2 - gx1) / 14.0f;

    if (tid < 14) {
        const float cy = ((float)tid + 0.5f) * hs + gy1;
        const float fl = floorf(cy);
        s_y0[tid] = (int)fl;
        s_y1[tid] = (int)ceilf(cy);
        s_ly[tid] = cy - fl;
    } else if (tid < 28) {
        const int j = tid - 14;
        const float cx = ((float)j + 0.5f) * ws + gx1;
        const float fl = floorf(cx);
        s_x0[j] = (int)fl;
        s_x1[j] = (int)ceilf(cx);
        s_lx[j] = cx - fl;
    }
    __syncthreads();

    const fp16* __restrict__ fb = ft + 4 * cg;   // channels 4cg..4cg+3

    const int pyBeg = half ? 4 : 0;
    const int pyEnd = half ? 7 : 4;

    for (int py = pyBeg; py < pyEnd; ++py) {
        float4 m[7];
        #pragma unroll
        for (int i = 0; i < 7; ++i) m[i] = make_float4(-3.0e38f, -3.0e38f, -3.0e38f, -3.0e38f);
        #pragma unroll
        for (int a = 0; a < 2; ++a) {
            const int sy = 2 * py + a;
            const float ly = s_ly[sy];
            const float oly = 1.0f - ly;
            const fp16* __restrict__ r0 = fb + (size_t)(s_y0[sy] * W) * 256;
            const fp16* __restrict__ r1 = fb + (size_t)(s_y1[sy] * W) * 256;
            #pragma unroll
            for (int sx = 0; sx < 14; ++sx) {
                const int x0 = s_x0[sx] * 256;
                const int x1 = s_x1[sx] * 256;
                const float lx = s_lx[sx];
                const float olx = 1.0f - lx;
                const float w00 = oly * olx, w01 = oly * lx;
                const float w10 = ly * olx,  w11 = ly * lx;
                const uint2 u00 = *(const uint2*)(r0 + x0);
                const uint2 u01 = *(const uint2*)(r0 + x1);
                const uint2 u10 = *(const uint2*)(r1 + x0);
                const uint2 u11 = *(const uint2*)(r1 + x1);
                const float2 a00 = __half22float2(*(const __half2*)&u00.x);
                const float2 b00 = __half22float2(*(const __half2*)&u00.y);
                const float2 a01 = __half22float2(*(const __half2*)&u01.x);
                const float2 b01 = __half22float2(*(const __half2*)&u01.y);
                const float2 a10 = __half22float2(*(const __half2*)&u10.x);
                const float2 b10 = __half22float2(*(const __half2*)&u10.y);
                const float2 a11 = __half22float2(*(const __half2*)&u11.x);
                const float2 b11 = __half22float2(*(const __half2*)&u11.y);
                float4& mm = m[sx >> 1];
                mm.x = fmaxf(mm.x, a00.x * w00 + a10.x * w10 + a01.x * w01 + a11.x * w11);
                mm.y = fmaxf(mm.y, a00.y * w00 + a10.y * w10 + a01.y * w01 + a11.y * w11);
                mm.z = fmaxf(mm.z, b00.x * w00 + b10.x * w10 + b01.x * w01 + b11.x * w11);
                mm.w = fmaxf(mm.w, b00.y * w00 + b10.y * w10 + b01.y * w01 + b11.y * w11);
            }
        }
        #pragma unroll
        for (int px = 0; px < 7; ++px) {
            const int cell = py * 7 + px;
            s[(4 * cg + 0) * 49 + cell] = m[px].x;
            s[(4 * cg + 1) * 49 + cell] = m[px].y;
            s[(4 * cg + 2) * 49 + cell] = m[px].z;
            s[(4 * cg + 3) * 49 + cell] = m[px].w;
        }
    }
    __syncthreads();

    const size_t ob = (size_t)r * DFEAT;
    for (int i = tid * 2; i < DFEAT; i += 256) {
        *(__half2*)(xh + ob + i) =
            __halves2half2(__float2half_rn(s[i]), __float2half_rn(s[i + 1]));
    }
}

// ---------------- HMMA GEMM, single-term fp16, GBK=128, 256 threads ------------
// A: [M][K] fp16 (K-major). B: [K][N] fp16 (N-major).
// Stage 48KB: A[128 rows][2x128B] @0, B[128 rows][128B] @32768.
// Each 128B block swizzled: chunk ^= row&7.
#define GBK 128
#define STG 4
#define BUF_SZ 49152
#define B_OFF 32768u
#define GEMM_SMEM (STG * BUF_SZ)   // 196608

__global__ __launch_bounds__(256) void gemm_mma(
    const fp16* __restrict__ Ah, const fp16* __restrict__ Bh,
    const float* __restrict__ bias, int K, int N, int mode,
    fp16* __restrict__ outH,
    float* __restrict__ outLoc, float* __restrict__ outSc, int outW)
{
    extern __shared__ char smem[];
    const uint32_t smU = s2u(smem);
    const int t   = threadIdx.x;
    const int l   = t & 31;
    const int wid = t >> 5;                 // 0..7
    const int wm  = (wid & 3) * 32;         // 4 warps over M=128
    const int wn  = (wid >> 2) * 32;        // 2 warps over N=64
    const int rowBase = blockIdx.x * 128;
    const int colBase = blockIdx.y * 64;
    const size_t K2 = (size_t)K * 2;

    // loader geometry: 32 rows per pass (t>>3), chunk c = t&7
    const int ldRow = t >> 3;
    const int ldC   = t & 7;
    const uint32_t ldSw = (((uint32_t)ldC ^ (uint32_t)(ldRow & 7)) << 4);

    const char* pAh = (const char*)(Ah + (size_t)(rowBase + ldRow) * K) + ldC * 16;
    const char* pB  = (const char*)(Bh + (size_t)ldRow * N + colBase) + ldC * 16;
    const size_t bStep = (size_t)GBK * N * 2;
    const size_t aRowStep32 = 32 * K2;
    const size_t bRowStep32 = 32 * (size_t)N * 2;

    float acc[2][4][4];
    #pragma unroll
    for (int mb = 0; mb < 2; ++mb)
        #pragma unroll
        for (int nb = 0; nb < 4; ++nb)
            #pragma unroll
            for (int i = 0; i < 4; ++i) acc[mb][nb][i] = 0.0f;

    // ldmatrix geometry (A rows now 256B wide: 2 x 128B halves)
    const uint32_t aRowAddr = (wm + (l & 15)) * 256;
    const uint32_t aSel = (uint32_t)((l & 15) & 7);
    const uint32_t aCk0 = (l >> 4);
    const uint32_t bLane = l & 15;
    const uint32_t bNg   = (uint32_t)(l >> 4);
    const uint32_t bCk0  = ((uint32_t)wn >> 3) + bNg;
    const uint32_t bCk1  = bCk0 + 2;

    const int nt = K / GBK;

    auto issue = [&](int kt) {
        const uint32_t bu = smU + (kt % STG) * BUF_SZ;
        const size_t ka = (size_t)kt * 256;     // bytes along K (128 fp16)
        const size_t kb = (size_t)kt * bStep;
        #pragma unroll
        for (int i = 0; i < 4; ++i) {
            const uint32_t sr = (uint32_t)(ldRow + i * 32) * 256;
            cp16(bu + sr + ldSw,        pAh + ka + i * aRowStep32);
            cp16(bu + sr + 128 + ldSw,  pAh + ka + i * aRowStep32 + 128);
        }
        #pragma unroll
        for (int i = 0; i < 4; ++i)
            cp16(bu + B_OFF + (uint32_t)(ldRow + i * 32) * 128 + ldSw,
                 pB + kb + i * bRowStep32);
        cp_commit();
    };

    issue(0);
    if (nt > 1) issue(1); else cp_commit();
    if (nt > 2) issue(2); else cp_commit();

    for (int kt = 0; kt < nt; ++kt) {
        cp_wait2();
        __syncthreads();
        if (kt + 3 < nt) issue(kt + 3);
        else cp_commit();

        const uint32_t bu = smU + (kt % STG) * BUF_SZ;
        const uint32_t aB = bu + aRowAddr;
        const uint32_t bB = bu + B_OFF;

        #pragma unroll
        for (int ks = 0; ks < 8; ++ks) {
            const uint32_t ck = aCk0 + 2 * ks;   // 0..15
            const uint32_t aOff = (ck >> 3) * 128 + (((ck & 7) ^ aSel) << 4);
            const uint32_t rowB = ks * 16 + bLane;   // 0..127
            const uint32_t rx = rowB & 7;
            const uint32_t bRow = rowB * 128;

            uint32_t af[2][4], bh[2][4];
            ldsm4(af[0], aB + aOff);
            ldsm4(af[1], aB + 4096 + aOff);     // +16 rows * 256B
            ldsm4t(bh[0], bB + bRow + (((bCk0 ^ rx)) << 4));
            ldsm4t(bh[1], bB + bRow + (((bCk1 ^ rx)) << 4));

            #pragma unroll
            for (int mb = 0; mb < 2; ++mb)
                #pragma unroll
                for (int nb = 0; nb < 4; ++nb)
                    mma16816(acc[mb][nb], af[mb], &bh[nb >> 1][2 * (nb & 1)]);
        }
    }

    // epilogue
    const int q = l >> 2, idx = l & 3;
    #pragma unroll
    for (int mb = 0; mb < 2; ++mb) {
        const int r0 = rowBase + wm + mb * 16 + q;
        const int r1 = r0 + 8;
        #pragma unroll
        for (int nb = 0; nb < 4; ++nb) {
            const int col = colBase + wn + nb * 8 + 2 * idx;
            if (mode == 0) {
                const float bs0 = bias[col], bs1 = bias[col + 1];
                const float v00 = fmaxf(acc[mb][nb][0] + bs0, 0.0f);
                const float v01 = fmaxf(acc[mb][nb][1] + bs1, 0.0f);
                const float v10 = fmaxf(acc[mb][nb][2] + bs0, 0.0f);
                const float v11 = fmaxf(acc[mb][nb][3] + bs1, 0.0f);
                *(__half2*)(outH + (size_t)r0 * outW + col) =
                    __halves2half2(__float2half_rn(v00), __float2half_rn(v01));
                *(__half2*)(outH + (size_t)r1 * outW + col) =
                    __halves2half2(__float2half_rn(v10), __float2half_rn(v11));
            } else {
                #pragma unroll
                for (int e = 0; e < 4; ++e) {
                    const int rr = (e < 2) ? r0 : r1;
                    const int cc = col + (e & 1);
                    if (rr < NROIS) {
                        const float v = acc[mb][nb][e] + bias[cc];
                        if (cc < 324)      outLoc[(size_t)rr * 324 + cc] = v;
                        else if (cc < 405) outSc[(size_t)rr * 81 + (cc - 324)] = v;
                    }
                }
            }
        }
    }
}

// ---------------- launch ------------------------------------------------------
extern "C" void kernel_launch(void* const* d_in, const int* in_sizes, int n_in,
                              void* d_out, int out_size)
{
    const float* f2   = (const float*)d_in[0];
    const float* f3   = (const float*)d_in[1];
    const float* f4   = (const float*)d_in[2];
    const float* f5   = (const float*)d_in[3];
    const float* rois = (const float*)d_in[4];
    const float* W1   = (const float*)d_in[6];
    const float* b1   = (const float*)d_in[7];
    const float* W2   = (const float*)d_in[8];
    const float* b2   = (const float*)d_in[9];
    const float* Wloc = (const float*)d_in[10];
    const float* bloc = (const float*)d_in[11];
    const float* Wsc  = (const float*)d_in[12];
    const float* bsc  = (const float*)d_in[13];

    float* out_loc = (float*)d_out;
    float* out_sc  = (float*)d_out + (size_t)NROIS * 324;

    fp16 *xh, *w1h, *w2h, *whh, *f1h, *f2h_;
    fp16 *ft2, *ft3, *ft4, *ft5;
    float *bcomb;
    cudaGetSymbolAddress((void**)&xh,   g_xh);
    cudaGetSymbolAddress((void**)&w1h,  g_w1h);
    cudaGetSymbolAddress((void**)&w2h,  g_w2h);
    cudaGetSymbolAddress((void**)&whh,  g_whh);
    cudaGetSymbolAddress((void**)&f1h,  g_f1h);
    cudaGetSymbolAddress((void**)&f2h_, g_f2h);
    cudaGetSymbolAddress((void**)&bcomb, g_bcomb);
    cudaGetSymbolAddress((void**)&ft2,  g_ft2);
    cudaGetSymbolAddress((void**)&ft3,  g_ft3);
    cudaGetSymbolAddress((void**)&ft4,  g_ft4);
    cudaGetSymbolAddress((void**)&ft5,  g_ft5);

    cudaFuncSetAttribute(gemm_mma, cudaFuncAttributeMaxDynamicSharedMemorySize, GEMM_SMEM);
    cudaFuncSetAttribute(roi_align3, cudaFuncAttributeMaxDynamicSharedMemorySize, DFEAT * 4);

    // launch 1: fused feature transpose + weight prep
    stage1_all<<<ST1_TOT, 256>>>(f2, f3, f4, f5, ft2, ft3, ft4, ft5,
                                 (const float4*)W1, (const float4*)W2,
                                 Wloc, Wsc, bloc, bsc,
                                 w1h, w2h, whh, bcomb);
    // launch 2: ROI align (fp16 out)
    roi_align3<<<NROIS, 128, DFEAT * 4>>>(ft2, ft3, ft4, ft5, rois, xh);

    // launch 3: big GEMM
    gemm_mma<<<dim3(8, 16), 256, GEMM_SMEM>>>(xh, w1h, b1, DFEAT, 1024, 0,
                                              f1h, nullptr, nullptr, 1024);
    // launch 4: fc2
    gemm_mma<<<dim3(8, 16), 256, GEMM_SMEM>>>(f1h, w2h, b2, 1024, 1024, 0,
                                              f2h_, nullptr, nullptr, 1024);
    // launch 5: heads
    gemm_mma<<<dim3(8, 7), 256, GEMM_SMEM>>>(f2h_, whh, bcomb, 1024, 512, 1,
                                             nullptr, out_loc, out_sc, 0);
}